// round 11
// baseline (speedup 1.0000x reference)
#include <cuda_runtime.h>
#include <cuda_bf16.h>
#include <math.h>
#include <stdint.h>

// Problem constants
#define B_    64
#define PANO_ 36
#define OBJ_  36
#define CFG_  16
#define LM_   8
#define IMG_  32
#define D_    300
#define H_    512
#define EMB_  64
#define ANG_  128
#define FEAT_ 2176
#define TOPN_ 3
#define M_    128
#define EPS_  1e-8f

// Output layout (flattened tuple): h_1 | c_1 | logit | h_tilde | ctx_attn
#define OFF_H1   0
#define OFF_C1   32768
#define OFF_LOG  65536
#define OFF_HT   67584
#define OFF_CA   100352

// ---------------- scratch ----------------
__device__ __align__(256) float g_x[B_*3140];      // [action_emb(64) | attn_feat(3076)]
__device__ __align__(256) float g_qfeat[B_*3076];
__device__ __align__(256) float g_cat[B_*1024];
__device__ __align__(256) float g_q2[B_*3097];
__device__ __align__(256) float g_gates[B_*2048];
__device__ __align__(256) float g_part[4*64*2048];  // W_ih split-K partials
__device__ __align__(256) float g_part2[4*64*512];  // att_in split-K partials
__device__ __align__(256) float g_pano_sim[B_*PANO_*900];
__device__ float g_a[B_*PANO_];
__device__ int   g_top1[B_*3];
__device__ float g_nb1[B_*3];
__device__ int   g_top2[B_*3];
__device__ float g_nb2[B_*3];
__device__ float g_relmask[B_*3];
__device__ float g_landrel[B_*18];

// ---------------- helpers ----------------
__device__ __forceinline__ float wred(float v) {
    #pragma unroll
    for (int o = 16; o; o >>= 1) v += __shfl_down_sync(0xffffffffu, v, o);
    return v;
}
__device__ __forceinline__ float block_reduce(float v, float* sbuf) {
    int lane = threadIdx.x & 31, w = threadIdx.x >> 5;
    v = wred(v);
    if (lane == 0) sbuf[w] = v;
    __syncthreads();
    int nw = blockDim.x >> 5;
    v = (threadIdx.x < nw) ? sbuf[threadIdx.x] : 0.f;
    if (w == 0) v = wred(v);
    return v;
}
__device__ __forceinline__ float sigmoidf_(float x) { return 1.f / (1.f + expf(-x)); }
__device__ __forceinline__ uint32_t to_tf32(float x) {
    uint32_t r; asm("cvt.rna.tf32.f32 %0, %1;" : "=r"(r) : "f"(x)); return r;
}
__device__ __forceinline__ void split_tf32(float x, uint32_t& hi, uint32_t& lo) {
    hi = to_tf32(x);
    lo = to_tf32(x - __uint_as_float(hi));
}
__device__ __forceinline__ void mma_tf32(float* acc, const uint32_t* a, const uint32_t* b) {
    asm volatile(
        "mma.sync.aligned.m16n8k8.row.col.f32.tf32.tf32.f32 "
        "{%0,%1,%2,%3}, {%4,%5,%6,%7}, {%8,%9}, {%0,%1,%2,%3};"
        : "+f"(acc[0]), "+f"(acc[1]), "+f"(acc[2]), "+f"(acc[3])
        : "r"(a[0]), "r"(a[1]), "r"(a[2]), "r"(a[3]), "r"(b[0]), "r"(b[1]));
}

// ---------------- GEMM args + body (TF32x3, splits precomputed in smem) ----------------
struct GArgs {
    const float* A; int lda;
    const float* W; int N; int K; int kChunk;
    float* out; const float* bias; int mode;   // 0 direct(+bias), 1 splitK partial, 2 direct+tanh
};

// smem layout (uint32): sAh[64*36], sAl[64*36], sWh[32*72], sWl[32*72]  = 9216 words = 36 KB
#define GEMM_SMEM_WORDS (64*36*2 + 32*72*2)

__device__ void gemm_body(const GArgs ga, int bx, int by, uint32_t* sm) {
    uint32_t* sAh = sm;
    uint32_t* sAl = sm + 64*36;
    uint32_t* sWh = sm + 64*36*2;
    uint32_t* sWl = sm + 64*36*2 + 32*72;
    const float* A = ga.A; const float* W = ga.W;
    int lda = ga.lda, N = ga.N, K = ga.K;
    int n0 = bx * 64;
    int k0 = by * ga.kChunk;
    int kEnd = min(K, k0 + ga.kChunk);
    bool w4 = ((N & 3) == 0);

    int tid  = threadIdx.x;
    int warp = tid >> 5, lane = tid & 31;
    int wm = warp >> 2, wn = warp & 3;
    int g  = lane >> 2, tg = lane & 3;

    float acc[2][2][4];
    #pragma unroll
    for (int mt = 0; mt < 2; mt++)
        #pragma unroll
        for (int nt = 0; nt < 2; nt++)
            #pragma unroll
            for (int e = 0; e < 4; e++) acc[mt][nt][e] = 0.f;

    for (int k = k0; k < kEnd; k += 32) {
        int kw = kEnd - k;
        // ---- A tile: 64 rows x 32 k, split once ----
        #pragma unroll
        for (int i = 0; i < 2; i++) {
            int idx = tid + i * 256;            // 512 float4 slots
            int r = idx >> 3, c = (idx & 7) * 4;
            float vv[4];
            if (c + 3 < kw) {
                float4 v = *(const float4*)(A + (size_t)r * lda + k + c);
                vv[0] = v.x; vv[1] = v.y; vv[2] = v.z; vv[3] = v.w;
            } else {
                #pragma unroll
                for (int e = 0; e < 4; e++)
                    vv[e] = (c + e < kw) ? A[(size_t)r * lda + k + c + e] : 0.f;
            }
            #pragma unroll
            for (int e = 0; e < 4; e++) {
                uint32_t hi, lo; split_tf32(vv[e], hi, lo);
                sAh[r * 36 + c + e] = hi;
                sAl[r * 36 + c + e] = lo;
            }
        }
        // ---- W tile: 32 k-rows x 64 cols, split once ----
        #pragma unroll
        for (int i = 0; i < 2; i++) {
            int idx = tid + i * 256;            // 512 float4 slots
            int r = idx >> 4, c = (idx & 15) * 4;
            int jg = n0 + c;
            float vv[4];
            if (r < kw && w4 && jg + 4 <= N) {
                float4 v = *(const float4*)(W + (size_t)(k + r) * N + jg);
                vv[0] = v.x; vv[1] = v.y; vv[2] = v.z; vv[3] = v.w;
            } else {
                #pragma unroll
                for (int e = 0; e < 4; e++)
                    vv[e] = (r < kw && jg + e < N) ? W[(size_t)(k + r) * N + jg + e] : 0.f;
            }
            #pragma unroll
            for (int e = 0; e < 4; e++) {
                uint32_t hi, lo; split_tf32(vv[e], hi, lo);
                sWh[r * 72 + c + e] = hi;
                sWl[r * 72 + c + e] = lo;
            }
        }
        __syncthreads();
        #pragma unroll
        for (int ks = 0; ks < 32; ks += 8) {
            uint32_t ah[2][4], al_[2][4], bh[2][2], bl_[2][2];
            #pragma unroll
            for (int mt = 0; mt < 2; mt++) {
                int mr = wm * 32 + mt * 16;
                ah[mt][0] = sAh[(mr + g    ) * 36 + ks + tg    ];
                ah[mt][1] = sAh[(mr + g + 8) * 36 + ks + tg    ];
                ah[mt][2] = sAh[(mr + g    ) * 36 + ks + tg + 4];
                ah[mt][3] = sAh[(mr + g + 8) * 36 + ks + tg + 4];
                al_[mt][0] = sAl[(mr + g    ) * 36 + ks + tg    ];
                al_[mt][1] = sAl[(mr + g + 8) * 36 + ks + tg    ];
                al_[mt][2] = sAl[(mr + g    ) * 36 + ks + tg + 4];
                al_[mt][3] = sAl[(mr + g + 8) * 36 + ks + tg + 4];
            }
            #pragma unroll
            for (int nt = 0; nt < 2; nt++) {
                int nc = wn * 16 + nt * 8;
                bh[nt][0] = sWh[(ks + tg    ) * 72 + nc + g];
                bh[nt][1] = sWh[(ks + tg + 4) * 72 + nc + g];
                bl_[nt][0] = sWl[(ks + tg    ) * 72 + nc + g];
                bl_[nt][1] = sWl[(ks + tg + 4) * 72 + nc + g];
            }
            #pragma unroll
            for (int mt = 0; mt < 2; mt++)
                #pragma unroll
                for (int nt = 0; nt < 2; nt++) {
                    mma_tf32(acc[mt][nt], al_[mt], bh[nt]);
                    mma_tf32(acc[mt][nt], ah[mt], bl_[nt]);
                    mma_tf32(acc[mt][nt], ah[mt], bh[nt]);
                }
        }
        __syncthreads();
    }

    float* Cp = ga.out + (ga.mode == 1 ? (size_t)by * 64 * N : 0);
    #pragma unroll
    for (int mt = 0; mt < 2; mt++)
        #pragma unroll
        for (int nt = 0; nt < 2; nt++) {
            int row  = wm * 32 + mt * 16 + g;
            int col0 = n0 + wn * 16 + nt * 8 + tg * 2;
            #pragma unroll
            for (int e = 0; e < 2; e++) {
                int col = col0 + e;
                if (col >= N) continue;
                float bb = (ga.bias && ga.mode != 1) ? ga.bias[col] : 0.f;
                float x0 = acc[mt][nt][e]     + bb;
                float x1 = acc[mt][nt][2 + e] + bb;
                if (ga.mode == 2) { x0 = tanhf(x0); x1 = tanhf(x1); }
                Cp[(size_t)row * N + col]       = x0;
                Cp[(size_t)(row + 8) * N + col] = x1;
            }
        }
}

__global__ void __launch_bounds__(256) k_gemm_tc(GArgs ga) {
    __shared__ uint32_t sm[GEMM_SMEM_WORDS];
    gemm_body(ga, blockIdx.x, blockIdx.y, sm);
}

__global__ void __launch_bounds__(256) k_gemm_pair(GArgs g0, int nb0, GArgs g1) {
    __shared__ uint32_t sm[GEMM_SMEM_WORDS];
    if ((int)blockIdx.x < nb0) gemm_body(g0, blockIdx.x, 0, sm);
    else                       gemm_body(g1, blockIdx.x - nb0, 0, sm);
}

// ---------------- top-k body ----------------
__device__ void topk_body(int b,
                          const float* __restrict__ score,
                          const float* __restrict__ lmask,
                          const float* __restrict__ land,
                          const float* __restrict__ relmask_in,
                          const float* __restrict__ landrel_in,
                          int which) {
    __shared__ float sv[128];
    __shared__ int sel[3];
    int tid = threadIdx.x;
    if (tid < 128) sv[tid] = score[b * 16 + (tid >> 3)] * lmask[b * 128 + tid];
    __syncthreads();
    int* top = which ? g_top2 : g_top1;
    float* nbout = which ? g_nb2 : g_nb1;
    if (tid < 32) {
        for (int r = 0; r < 3; r++) {
            float bv = -INFINITY; int bi = 128;
            for (int m = tid; m < 128; m += 32) {
                float v = sv[m];
                if (v > bv || (v == bv && m < bi)) { bv = v; bi = m; }
            }
            #pragma unroll
            for (int off = 16; off; off >>= 1) {
                float ov = __shfl_down_sync(0xffffffffu, bv, off);
                int   oi = __shfl_down_sync(0xffffffffu, bi, off);
                if (ov > bv || (ov == bv && oi < bi)) { bv = ov; bi = oi; }
            }
            if (tid == 0) { sel[r] = bi; top[b * 3 + r] = bi; sv[bi] = -INFINITY; }
            __syncwarp();
        }
    }
    __syncthreads();
    int w = tid >> 5, lane = tid & 31;
    if (w < 3) {
        int m = sel[w];
        const float* p = land + ((size_t)b * 128 + m) * D_;
        float s = 0.f;
        for (int d = lane; d < D_; d += 32) { float v = p[d]; s += v * v; }
        s = wred(s);
        if (lane == 0) nbout[b * 3 + w] = sqrtf(s);
    }
    if (relmask_in && tid < 3)
        g_relmask[b * 3 + tid] = relmask_in[b * 128 + sel[tid]];
    if (landrel_in && tid < 18) {
        int t = tid / 6, r2 = tid % 6;
        g_landrel[b * 18 + tid] = landrel_in[((size_t)b * 128 + sel[t]) * 6 + r2];
    }
}

// ---------------- merged: action embedding (16 blocks) + topk1 (64 blocks) ----------------
__global__ void __launch_bounds__(256) k_misc1(
        const float* __restrict__ action, const float* __restrict__ embW,
        const float* __restrict__ embB,
        const float* __restrict__ s_0, const float* __restrict__ lmask,
        const float* __restrict__ land) {
    if (blockIdx.x < 16) {
        int idx = blockIdx.x * 256 + threadIdx.x;
        if (idx >= B_ * EMB_) return;
        int b = idx >> 6, e = idx & 63;
        float acc = embB[e];
        const float* a = action + b * ANG_;
        #pragma unroll 4
        for (int k = 0; k < ANG_; k++) acc += a[k] * embW[k * EMB_ + e];
        g_x[(size_t)b * 3140 + e] = tanhf(acc);
    } else {
        topk_body(blockIdx.x - 16, s_0, lmask, land, nullptr, nullptr, 0);
    }
}

// ---------------- merged: att_out GEMM (8 blocks, tanh) + topk2 (64 blocks) ----------------
__global__ void __launch_bounds__(256) k_attout_topk(
        GArgs ga,
        const float* __restrict__ ctx_attn_out, const float* __restrict__ lmask,
        const float* __restrict__ land,
        const float* __restrict__ relmask_in, const float* __restrict__ landrel_in) {
    if (blockIdx.x < 8) {
        __shared__ uint32_t sm[GEMM_SMEM_WORDS];
        gemm_body(ga, blockIdx.x, 0, sm);
    } else {
        topk_body(blockIdx.x - 8, ctx_attn_out, lmask, land, relmask_in, landrel_in, 1);
    }
}

// ---------------- fused object retrieval + dot-with-query (float4) ----------------
__global__ void __launch_bounds__(256) k_objret(
        const float* __restrict__ obj, int I,
        const float* __restrict__ land,
        const float* __restrict__ extra,      // feature or cand_feat [B,I,FEAT]
        const float* __restrict__ qbase,      // g_qfeat or g_q2
        const float* __restrict__ crel,       // [B,IMG,6] (which=1 only)
        float* __restrict__ aout, int which) {
    int bi = blockIdx.x;
    int b = bi / I;
    __shared__ float4 sl4[3][75];
    __shared__ float snb[3];
    __shared__ float ssim[OBJ_][3];
    __shared__ int sbest[3];
    __shared__ float sred[8];
    int tid = threadIdx.x;
    const int* top = which ? g_top2 : g_top1;
    const float* nb = which ? g_nb2 : g_nb1;
    if (tid < 225) {
        int t = tid / 75, i = tid % 75;
        sl4[t][i] = ((const float4*)(land + ((size_t)b * 128 + top[b * 3 + t]) * D_))[i];
    }
    if (tid < 3) snb[tid] = nb[b * 3 + tid];
    __syncthreads();

    const float* ob = obj + (size_t)bi * OBJ_ * D_;
    int w = tid >> 5, lane = tid & 31;
    for (int o = w; o < OBJ_; o += 8) {
        const float4* po4 = (const float4*)(ob + o * D_);
        float d0 = 0.f, d1 = 0.f, d2 = 0.f, nr = 0.f;
        #pragma unroll 3
        for (int i = lane; i < 75; i += 32) {
            float4 v  = po4[i];
            float4 a0 = sl4[0][i], a1 = sl4[1][i], a2 = sl4[2][i];
            d0 += v.x*a0.x + v.y*a0.y + v.z*a0.z + v.w*a0.w;
            d1 += v.x*a1.x + v.y*a1.y + v.z*a1.z + v.w*a1.w;
            d2 += v.x*a2.x + v.y*a2.y + v.z*a2.z + v.w*a2.w;
            nr += v.x*v.x  + v.y*v.y  + v.z*v.z  + v.w*v.w;
        }
        #pragma unroll
        for (int off = 16; off; off >>= 1) {
            d0 += __shfl_down_sync(0xffffffffu, d0, off);
            d1 += __shfl_down_sync(0xffffffffu, d1, off);
            d2 += __shfl_down_sync(0xffffffffu, d2, off);
            nr += __shfl_down_sync(0xffffffffu, nr, off);
        }
        if (lane == 0) {
            float na = sqrtf(nr);
            ssim[o][0] = d0 / fmaxf(na * snb[0], EPS_);
            ssim[o][1] = d1 / fmaxf(na * snb[1], EPS_);
            ssim[o][2] = d2 / fmaxf(na * snb[2], EPS_);
        }
    }
    __syncthreads();
    if (tid < 3) {
        float bv = -INFINITY; int bo = 0;
        for (int o = 0; o < OBJ_; o++) { float v = ssim[o][tid]; if (v > bv) { bv = v; bo = o; } }
        sbest[tid] = bo;
    }
    __syncthreads();

    int qStride = which ? 3097 : 3076;
    int tStride = which ? 307  : 300;
    const float* q = qbase + (size_t)b * qStride;
    float accq = 0.f;
    // base feature dot (f via float4, q scalar — q row alignment varies)
    const float4* f4 = (const float4*)(extra + (size_t)bi * FEAT_);
    #pragma unroll 2
    for (int i = tid; i < FEAT_/4; i += 256) {
        float4 v = f4[i];
        int d = i * 4;
        accq += v.x*q[d] + v.y*q[d+1] + v.z*q[d+2] + v.w*q[d+3];
    }
    // gathered-object dot (+ pano_sim write)
    if (tid < 225) {
        int t = tid / 75, i = tid % 75, d = i * 4;
        float4 v = ((const float4*)(ob + sbest[t] * D_))[i];
        if (!which) ((float4*)(g_pano_sim + (size_t)bi * 900 + t * 300))[i] = v;
        const float* qq = q + FEAT_ + t * tStride + d;
        accq += v.x*qq[0] + v.y*qq[1] + v.z*qq[2] + v.w*qq[3];
    }
    // relation terms (cand only)
    if (which && tid < 21) {
        int t = tid / 7, r = tid % 7;
        const float* cr = crel + (size_t)bi * 6;
        if (r < 6) {
            accq += cr[r] * g_relmask[b * 3 + t] * q[FEAT_ + t * 307 + 300 + r];
        } else {
            float dot = 0.f;
            #pragma unroll
            for (int rr = 0; rr < 6; rr++) dot += cr[rr] * g_landrel[b * 18 + t * 6 + rr];
            accq += dot * q[FEAT_ + t * 307 + 306];
        }
    }
    accq = block_reduce(accq, sred);
    if (tid == 0) aout[bi] = accq;
}

// ---------------- attention-weighted feature (softmax inline) ----------------
__global__ void k_attn_feat(const float* __restrict__ feature) {
    int b = blockIdx.y;
    int d = blockIdx.x * 256 + threadIdx.x;
    __shared__ float sp[PANO_];
    __shared__ float sms[2];
    if (threadIdx.x < PANO_) sp[threadIdx.x] = g_a[b * PANO_ + threadIdx.x];
    __syncthreads();
    if (threadIdx.x == 0) {
        float m = -INFINITY;
        for (int i = 0; i < PANO_; i++) m = fmaxf(m, sp[i]);
        float su = 0.f;
        for (int i = 0; i < PANO_; i++) su += expf(sp[i] - m);
        sms[0] = m; sms[1] = su;
    }
    __syncthreads();
    if (threadIdx.x < PANO_)
        sp[threadIdx.x] = expf(sp[threadIdx.x] - sms[0]) / sms[1];
    __syncthreads();
    if (d >= 3076) return;
    float acc = 0.f;
    if (d < FEAT_) {
        const float* f = feature + (size_t)b * PANO_ * FEAT_ + d;
        #pragma unroll 4
        for (int s = 0; s < PANO_; s++) acc += sp[s] * f[(size_t)s * FEAT_];
    } else {
        const float* f = g_pano_sim + (size_t)b * PANO_ * 900 + (d - FEAT_);
        #pragma unroll 4
        for (int s = 0; s < PANO_; s++) acc += sp[s] * f[(size_t)s * 900];
    }
    g_x[(size_t)b * 3140 + 64 + d] = acc;
}

// ---------------- LSTM (fused split-K reduce + bias) ----------------
__global__ void k_lstm(const float* __restrict__ c0,
                       const float* __restrict__ bias,
                       float* __restrict__ out) {
    int idx = blockIdx.x * 256 + threadIdx.x;
    if (idx >= B_ * H_) return;
    int b = idx >> 9, j = idx & 511;
    float g4[4];
    #pragma unroll
    for (int qg = 0; qg < 4; qg++) {
        int col = qg * 512 + j;
        float v = bias[col] + g_gates[(size_t)b * 2048 + col];
        #pragma unroll
        for (int s = 0; s < 4; s++)
            v += g_part[(size_t)s * 64 * 2048 + (size_t)b * 2048 + col];
        g4[qg] = v;
    }
    float ig = sigmoidf_(g4[0]);
    float fg = sigmoidf_(g4[1]);
    float gg = tanhf(g4[2]);
    float og = sigmoidf_(g4[3]);
    float c1 = fg * c0[idx] + ig * gg;
    float h1 = og * tanhf(c1);
    out[OFF_H1 + idx] = h1;
    out[OFF_C1 + idx] = c1;
}

// ---------------- ctx attention (fused att_in split-K reduce) ----------------
__global__ void k_ctx_attn(const float* __restrict__ ctx,
                           const unsigned char* __restrict__ cmask,
                           float* __restrict__ out) {
    int b = blockIdx.x;
    int tid = threadIdx.x; // 512
    __shared__ float sqa[H_], slg[CFG_], sattn[CFG_];
    {
        float v = 0.f;
        #pragma unroll
        for (int s = 0; s < 4; s++)
            v += g_part2[(size_t)s * 64 * 512 + (size_t)b * 512 + tid];
        sqa[tid] = v;
    }
    __syncthreads();
    int w = tid >> 5, lane = tid & 31;
    const float* cb = ctx + (size_t)b * CFG_ * H_;
    {
        float acc = 0.f;
        const float* cw = cb + w * H_;
        for (int d = lane; d < H_; d += 32) acc += cw[d] * sqa[d];
        acc = wred(acc);
        if (lane == 0) slg[w] = cmask[b * CFG_ + w] ? -INFINITY : acc;
    }
    __syncthreads();
    if (tid == 0) {
        float m = -INFINITY;
        for (int s = 0; s < CFG_; s++) m = fmaxf(m, slg[s]);
        float su = 0.f;
        for (int s = 0; s < CFG_; s++) { float e = expf(slg[s] - m); sattn[s] = e; su += e; }
        float inv = 1.f / su;
        for (int s = 0; s < CFG_; s++) { sattn[s] *= inv; out[OFF_CA + b * CFG_ + s] = sattn[s]; }
    }
    __syncthreads();
    float acc = 0.f;
    #pragma unroll
    for (int s = 0; s < CFG_; s++) acc += sattn[s] * cb[(size_t)s * H_ + tid];
    g_cat[b * 1024 + tid] = acc;
    g_cat[b * 1024 + 512 + tid] = out[OFF_H1 + b * H_ + tid];
}

// ---------------- host launcher ----------------
extern "C" void kernel_launch(void* const* d_in, const int* in_sizes, int n_in,
                              void* d_out, int out_size) {
    const float* action    = (const float*)d_in[0];
    const float* feature   = (const float*)d_in[1];
    const float* cand_feat = (const float*)d_in[2];
    const float* prev_h1   = (const float*)d_in[3];
    const float* c_0       = (const float*)d_in[4];
    const float* ctx       = (const float*)d_in[5];
    const float* s_0       = (const float*)d_in[6];
    const float* land      = (const float*)d_in[7];
    const float* cand_obj  = (const float*)d_in[8];
    const float* lmask     = (const float*)d_in[9];
    const float* landrel   = (const float*)d_in[10];
    const float* relmask   = (const float*)d_in[11];
    const float* crel      = (const float*)d_in[12];
    const float* pano_obj  = (const float*)d_in[13];
    const float* embW      = (const float*)d_in[14];
    const float* embB      = (const float*)d_in[15];
    const float* W_ih      = (const float*)d_in[16];
    const float* W_hh      = (const float*)d_in[17];
    const float* b_lstm    = (const float*)d_in[18];
    const float* feat_in_W = (const float*)d_in[19];
    const float* att_in_W  = (const float*)d_in[20];
    const float* att_out_W = (const float*)d_in[21];
    const float* cand_in_W = (const float*)d_in[22];
    const unsigned char* cmask = (const unsigned char*)d_in[23];
    float* out = (float*)d_out;

    float *p_x, *p_qfeat, *p_gates, *p_cat, *p_q2, *p_part, *p_part2, *p_a;
    cudaGetSymbolAddress((void**)&p_x,     g_x);
    cudaGetSymbolAddress((void**)&p_qfeat, g_qfeat);
    cudaGetSymbolAddress((void**)&p_gates, g_gates);
    cudaGetSymbolAddress((void**)&p_cat,   g_cat);
    cudaGetSymbolAddress((void**)&p_q2,    g_q2);
    cudaGetSymbolAddress((void**)&p_part,  g_part);
    cudaGetSymbolAddress((void**)&p_part2, g_part2);
    cudaGetSymbolAddress((void**)&p_a,     g_a);

    // 1) action embedding + topk1
    k_misc1<<<80, 256>>>(action, embW, embB, s_0, lmask, land);

    // 2) qfeat = prev_h1 @ feat_in_W  AND  gates_hh = prev_h1 @ W_hh (batched)
    GArgs ga_qf  = { prev_h1, 512, feat_in_W, 3076, 512, 512, p_qfeat, nullptr, 0 };
    GArgs ga_hh  = { prev_h1, 512, W_hh,      2048, 512, 512, p_gates, nullptr, 0 };
    k_gemm_pair<<<81, 256>>>(ga_qf, 49, ga_hh);

    // 3) pano object retrieval + feature-attention logits
    k_objret<<<B_ * PANO_, 256>>>(pano_obj, PANO_, land, feature, p_qfeat, nullptr, p_a, 0);

    // 4) attention-weighted feature (softmax inline)
    k_attn_feat<<<dim3(13, B_), 256>>>(feature);

    // 5) gates_ih = x @ W_ih  (split-K 4)
    GArgs ga_ih = { p_x, 3140, W_ih, 2048, 3140, 800, p_part, nullptr, 1 };
    k_gemm_tc<<<dim3(32, 4), 256>>>(ga_ih);

    // 6) LSTM pointwise (reduces ih partials + hh + bias)
    k_lstm<<<128, 256>>>(c_0, b_lstm, out);

    // 7) qa = h1 @ att_in_W  (split-K 4 -> partials, reduced in ctx_attn)
    GArgs ga_ai = { out + OFF_H1, 512, att_in_W, 512, 512, 128, p_part2, nullptr, 1 };
    k_gemm_tc<<<dim3(8, 4), 256>>>(ga_ai);

    // 8) ctx attention
    k_ctx_attn<<<B_, 512>>>(ctx, cmask, out);

    // 9) h_tilde = tanh(cat @ att_out_W)  AND  topk2 (merged)
    GArgs ga_ao = { p_cat, 1024, att_out_W, 512, 1024, 1024, out + OFF_HT, nullptr, 2 };
    k_attout_topk<<<72, 256>>>(ga_ao, out + OFF_CA, lmask, land, relmask, landrel);

    // 10) q2 = h_tilde @ cand_in_W
    GArgs ga_q2 = { out + OFF_HT, 512, cand_in_W, 3097, 512, 512, p_q2, nullptr, 0 };
    k_gemm_tc<<<dim3(49, 1), 256>>>(ga_q2);

    // 11) candidate retrieval + final logit
    k_objret<<<B_ * IMG_, 256>>>(cand_obj, IMG_, land, cand_feat, p_q2, crel, out + OFF_LOG, 1);
}

// round 12
// speedup vs baseline: 1.3789x; 1.3789x over previous
#include <cuda_runtime.h>
#include <cuda_bf16.h>
#include <math.h>
#include <stdint.h>

// Problem constants
#define B_    64
#define PANO_ 36
#define OBJ_  36
#define CFG_  16
#define LM_   8
#define IMG_  32
#define D_    300
#define H_    512
#define EMB_  64
#define ANG_  128
#define FEAT_ 2176
#define TOPN_ 3
#define M_    128
#define EPS_  1e-8f

// Output layout (flattened tuple): h_1 | c_1 | logit | h_tilde | ctx_attn
#define OFF_H1   0
#define OFF_C1   32768
#define OFF_LOG  65536
#define OFF_HT   67584
#define OFF_CA   100352

// ---------------- scratch ----------------
__device__ __align__(256) float g_x[B_*3140];       // [action_emb(64) | attn_feat(3076)]
__device__ __align__(256) float g_qfeat[B_*3076];
__device__ __align__(256) float g_cat[B_*1024];
__device__ __align__(256) float g_q2[B_*3097];
__device__ __align__(256) float g_part[800000];     // generic split-K partials (qfeat / ih / q2)
__device__ __align__(256) float g_parthh[4*64*2048];
__device__ __align__(256) float g_part2[8*64*512];  // att_in (8 sets) then att_out (8 sets)
__device__ __align__(256) float g_pano_sim[B_*PANO_*900];
__device__ float g_a[B_*PANO_];
__device__ int   g_top1[B_*3];
__device__ float g_nb1[B_*3];
__device__ int   g_top2[B_*3];
__device__ float g_nb2[B_*3];
__device__ float g_relmask[B_*3];
__device__ float g_landrel[B_*18];

// ---------------- helpers ----------------
__device__ __forceinline__ float wred(float v) {
    #pragma unroll
    for (int o = 16; o; o >>= 1) v += __shfl_down_sync(0xffffffffu, v, o);
    return v;
}
__device__ __forceinline__ float block_reduce(float v, float* sbuf) {
    int lane = threadIdx.x & 31, w = threadIdx.x >> 5;
    v = wred(v);
    if (lane == 0) sbuf[w] = v;
    __syncthreads();
    int nw = blockDim.x >> 5;
    v = (threadIdx.x < nw) ? sbuf[threadIdx.x] : 0.f;
    if (w == 0) v = wred(v);
    return v;
}
__device__ __forceinline__ float sigmoidf_(float x) { return 1.f / (1.f + expf(-x)); }

// ---------------- FFMA split-K GEMM body (R6-proven, float4 loads) ----------------
// part[ky][b][j] = sum_{k in chunk ky} A[b,k] * W[k,j]
__device__ void gemm64_body(const float* __restrict__ A, int lda,
                            const float* __restrict__ W, int N, int K,
                            int kChunk, float* __restrict__ part,
                            int jbi, int ky) {
    __shared__ float sA[16][64];
    __shared__ float sW[16][64];
    int jb = jbi * 64;
    int k0 = ky * kChunk;
    int kEnd = min(K, k0 + kChunk);
    int tid = threadIdx.x;                 // 128 threads
    int tj = tid & 15, tb = tid >> 4;
    float acc[8][4];
    #pragma unroll
    for (int r = 0; r < 8; r++)
        #pragma unroll
        for (int c = 0; c < 4; c++) acc[r][c] = 0.f;
    int la_b = tid >> 1, la_k = (tid & 1) * 8;
    int lw_k = tid >> 3, lw_j = (tid & 7) * 8;
    bool wAligned = ((N & 3) == 0);
    for (int k = k0; k < kEnd; k += 16) {
        int kw = kEnd - k;
        // A tile (transposed stage)
        if (la_k + 8 <= kw) {
            const float* ap = A + (size_t)la_b * lda + k + la_k;
            float4 v0 = *(const float4*)ap;
            float4 v1 = *(const float4*)(ap + 4);
            sA[la_k+0][la_b] = v0.x; sA[la_k+1][la_b] = v0.y;
            sA[la_k+2][la_b] = v0.z; sA[la_k+3][la_b] = v0.w;
            sA[la_k+4][la_b] = v1.x; sA[la_k+5][la_b] = v1.y;
            sA[la_k+6][la_b] = v1.z; sA[la_k+7][la_b] = v1.w;
        } else {
            #pragma unroll
            for (int e = 0; e < 8; e++) {
                int kk = la_k + e;
                sA[kk][la_b] = (kk < kw) ? A[(size_t)la_b * lda + k + kk] : 0.f;
            }
        }
        // W tile
        int kg = k + lw_k;
        int jg0 = jb + lw_j;
        if (lw_k < kw && wAligned && jg0 + 8 <= N) {
            const float* wp = W + (size_t)kg * N + jg0;
            float4 w0 = *(const float4*)wp;
            float4 w1 = *(const float4*)(wp + 4);
            sW[lw_k][lw_j+0] = w0.x; sW[lw_k][lw_j+1] = w0.y;
            sW[lw_k][lw_j+2] = w0.z; sW[lw_k][lw_j+3] = w0.w;
            sW[lw_k][lw_j+4] = w1.x; sW[lw_k][lw_j+5] = w1.y;
            sW[lw_k][lw_j+6] = w1.z; sW[lw_k][lw_j+7] = w1.w;
        } else {
            #pragma unroll
            for (int e = 0; e < 8; e++) {
                int jg = jg0 + e;
                sW[lw_k][lw_j+e] = (lw_k < kw && jg < N) ? W[(size_t)kg * N + jg] : 0.f;
            }
        }
        __syncthreads();
        #pragma unroll
        for (int kk = 0; kk < 16; kk++) {
            float av[8], wv[4];
            #pragma unroll
            for (int r = 0; r < 8; r++) av[r] = sA[kk][tb * 8 + r];
            #pragma unroll
            for (int c = 0; c < 4; c++) wv[c] = sW[kk][tj * 4 + c];
            #pragma unroll
            for (int r = 0; r < 8; r++)
                #pragma unroll
                for (int c = 0; c < 4; c++) acc[r][c] += av[r] * wv[c];
        }
        __syncthreads();
    }
    float* pp = part + (size_t)ky * 64 * N;
    #pragma unroll
    for (int r = 0; r < 8; r++) {
        int b = tb * 8 + r;
        #pragma unroll
        for (int c = 0; c < 4; c++) {
            int j = jb + tj * 4 + c;
            if (j < N) pp[(size_t)b * N + j] = acc[r][c];
        }
    }
}

__global__ void __launch_bounds__(128) k_gemm64(
        const float* __restrict__ A, int lda, const float* __restrict__ W,
        int N, int K, int kChunk, float* __restrict__ part) {
    gemm64_body(A, lda, W, N, K, kChunk, part, blockIdx.x, blockIdx.y);
}

// Two GEMMs batched in one launch (independent, both read prev_h1)
__global__ void __launch_bounds__(128) k_gemm_pair64(
        const float* __restrict__ A0, int lda0, const float* __restrict__ W0,
        int N0, int K0, int kc0, float* __restrict__ p0, int njb0, int nb0,
        const float* __restrict__ A1, int lda1, const float* __restrict__ W1,
        int N1, int K1, int kc1, float* __restrict__ p1, int njb1) {
    int bid = blockIdx.x;
    if (bid < nb0) gemm64_body(A0, lda0, W0, N0, K0, kc0, p0, bid % njb0, bid / njb0);
    else {
        bid -= nb0;
        gemm64_body(A1, lda1, W1, N1, K1, kc1, p1, bid % njb1, bid / njb1);
    }
}

__global__ void k_reduce(const float* __restrict__ part, int S, int N,
                         float* __restrict__ C) {
    int idx = blockIdx.x * 256 + threadIdx.x;
    int MN = 64 * N;
    if (idx >= MN) return;
    float v = 0.f;
    for (int s = 0; s < S; s++) v += part[(size_t)s * MN + idx];
    C[idx] = v;
}

// ---------------- top-k body ----------------
__device__ void topk_body(int b,
                          const float* __restrict__ score,
                          const float* __restrict__ lmask,
                          const float* __restrict__ land,
                          const float* __restrict__ relmask_in,
                          const float* __restrict__ landrel_in,
                          int which) {
    __shared__ float sv[128];
    __shared__ int sel[3];
    int tid = threadIdx.x;
    if (tid < 128) sv[tid] = score[b * 16 + (tid >> 3)] * lmask[b * 128 + tid];
    __syncthreads();
    int* top = which ? g_top2 : g_top1;
    float* nbout = which ? g_nb2 : g_nb1;
    if (tid < 32) {
        for (int r = 0; r < 3; r++) {
            float bv = -INFINITY; int bi = 128;
            for (int m = tid; m < 128; m += 32) {
                float v = sv[m];
                if (v > bv || (v == bv && m < bi)) { bv = v; bi = m; }
            }
            #pragma unroll
            for (int off = 16; off; off >>= 1) {
                float ov = __shfl_down_sync(0xffffffffu, bv, off);
                int   oi = __shfl_down_sync(0xffffffffu, bi, off);
                if (ov > bv || (ov == bv && oi < bi)) { bv = ov; bi = oi; }
            }
            if (tid == 0) { sel[r] = bi; top[b * 3 + r] = bi; sv[bi] = -INFINITY; }
            __syncwarp();
        }
    }
    __syncthreads();
    int w = tid >> 5, lane = tid & 31;
    if (w < 3) {
        int m = sel[w];
        const float* p = land + ((size_t)b * 128 + m) * D_;
        float s = 0.f;
        for (int d = lane; d < D_; d += 32) { float v = p[d]; s += v * v; }
        s = wred(s);
        if (lane == 0) nbout[b * 3 + w] = sqrtf(s);
    }
    if (relmask_in && tid < 3)
        g_relmask[b * 3 + tid] = relmask_in[b * 128 + sel[tid]];
    if (landrel_in && tid < 18) {
        int t = tid / 6, r2 = tid % 6;
        g_landrel[b * 18 + tid] = landrel_in[((size_t)b * 128 + sel[t]) * 6 + r2];
    }
}

// ---------------- merged: action embedding (16 blocks) + topk1 (64 blocks) ----------------
__global__ void __launch_bounds__(256) k_misc1(
        const float* __restrict__ action, const float* __restrict__ embW,
        const float* __restrict__ embB,
        const float* __restrict__ s_0, const float* __restrict__ lmask,
        const float* __restrict__ land) {
    if (blockIdx.x < 16) {
        int idx = blockIdx.x * 256 + threadIdx.x;
        if (idx >= B_ * EMB_) return;
        int b = idx >> 6, e = idx & 63;
        float acc = embB[e];
        const float* a = action + b * ANG_;
        #pragma unroll 4
        for (int k = 0; k < ANG_; k++) acc += a[k] * embW[k * EMB_ + e];
        g_x[(size_t)b * 3140 + e] = tanhf(acc);
    } else {
        topk_body(blockIdx.x - 16, s_0, lmask, land, nullptr, nullptr, 0);
    }
}

// ---------------- merged: att_out GEMM (64 blocks, splitK) + topk2 (64 blocks) ----------------
__global__ void __launch_bounds__(128) k_attout_topk(
        const float* __restrict__ A, const float* __restrict__ W,
        const float* __restrict__ ctx_attn_out, const float* __restrict__ lmask,
        const float* __restrict__ land,
        const float* __restrict__ relmask_in, const float* __restrict__ landrel_in) {
    if (blockIdx.x < 64) {
        gemm64_body(A, 1024, W, 512, 1024, 128, g_part2, blockIdx.x & 7, blockIdx.x >> 3);
    } else {
        topk_body(blockIdx.x - 64, ctx_attn_out, lmask, land, relmask_in, landrel_in, 1);
    }
}

// ---------------- fused object retrieval + dot-with-query (float4) ----------------
__global__ void __launch_bounds__(256) k_objret(
        const float* __restrict__ obj, int I,
        const float* __restrict__ land,
        const float* __restrict__ extra,      // feature or cand_feat [B,I,FEAT]
        const float* __restrict__ qbase,      // g_qfeat or g_q2
        const float* __restrict__ crel,       // [B,IMG,6] (which=1 only)
        float* __restrict__ aout, int which) {
    int bi = blockIdx.x;
    int b = bi / I;
    __shared__ float4 sl4[3][75];
    __shared__ float snb[3];
    __shared__ float ssim[OBJ_][3];
    __shared__ int sbest[3];
    __shared__ float sred[8];
    int tid = threadIdx.x;
    const int* top = which ? g_top2 : g_top1;
    const float* nb = which ? g_nb2 : g_nb1;
    if (tid < 225) {
        int t = tid / 75, i = tid % 75;
        sl4[t][i] = ((const float4*)(land + ((size_t)b * 128 + top[b * 3 + t]) * D_))[i];
    }
    if (tid < 3) snb[tid] = nb[b * 3 + tid];
    __syncthreads();

    const float* ob = obj + (size_t)bi * OBJ_ * D_;
    int w = tid >> 5, lane = tid & 31;
    for (int o = w; o < OBJ_; o += 8) {
        const float4* po4 = (const float4*)(ob + o * D_);
        float d0 = 0.f, d1 = 0.f, d2 = 0.f, nr = 0.f;
        #pragma unroll 3
        for (int i = lane; i < 75; i += 32) {
            float4 v  = po4[i];
            float4 a0 = sl4[0][i], a1 = sl4[1][i], a2 = sl4[2][i];
            d0 += v.x*a0.x + v.y*a0.y + v.z*a0.z + v.w*a0.w;
            d1 += v.x*a1.x + v.y*a1.y + v.z*a1.z + v.w*a1.w;
            d2 += v.x*a2.x + v.y*a2.y + v.z*a2.z + v.w*a2.w;
            nr += v.x*v.x  + v.y*v.y  + v.z*v.z  + v.w*v.w;
        }
        #pragma unroll
        for (int off = 16; off; off >>= 1) {
            d0 += __shfl_down_sync(0xffffffffu, d0, off);
            d1 += __shfl_down_sync(0xffffffffu, d1, off);
            d2 += __shfl_down_sync(0xffffffffu, d2, off);
            nr += __shfl_down_sync(0xffffffffu, nr, off);
        }
        if (lane == 0) {
            float na = sqrtf(nr);
            ssim[o][0] = d0 / fmaxf(na * snb[0], EPS_);
            ssim[o][1] = d1 / fmaxf(na * snb[1], EPS_);
            ssim[o][2] = d2 / fmaxf(na * snb[2], EPS_);
        }
    }
    __syncthreads();
    if (tid < 3) {
        float bv = -INFINITY; int bo = 0;
        for (int o = 0; o < OBJ_; o++) { float v = ssim[o][tid]; if (v > bv) { bv = v; bo = o; } }
        sbest[tid] = bo;
    }
    __syncthreads();

    int qStride = which ? 3097 : 3076;
    int tStride = which ? 307  : 300;
    const float* q = qbase + (size_t)b * qStride;
    float accq = 0.f;
    const float4* f4 = (const float4*)(extra + (size_t)bi * FEAT_);
    #pragma unroll 2
    for (int i = tid; i < FEAT_/4; i += 256) {
        float4 v = f4[i];
        int d = i * 4;
        accq += v.x*q[d] + v.y*q[d+1] + v.z*q[d+2] + v.w*q[d+3];
    }
    if (tid < 225) {
        int t = tid / 75, i = tid % 75, d = i * 4;
        float4 v = ((const float4*)(ob + sbest[t] * D_))[i];
        if (!which) ((float4*)(g_pano_sim + (size_t)bi * 900 + t * 300))[i] = v;
        const float* qq = q + FEAT_ + t * tStride + d;
        accq += v.x*qq[0] + v.y*qq[1] + v.z*qq[2] + v.w*qq[3];
    }
    if (which && tid < 21) {
        int t = tid / 7, r = tid % 7;
        const float* cr = crel + (size_t)bi * 6;
        if (r < 6) {
            accq += cr[r] * g_relmask[b * 3 + t] * q[FEAT_ + t * 307 + 300 + r];
        } else {
            float dot = 0.f;
            #pragma unroll
            for (int rr = 0; rr < 6; rr++) dot += cr[rr] * g_landrel[b * 18 + t * 6 + rr];
            accq += dot * q[FEAT_ + t * 307 + 306];
        }
    }
    accq = block_reduce(accq, sred);
    if (tid == 0) aout[bi] = accq;
}

// ---------------- attention-weighted feature (softmax inline, float4) ----------------
__global__ void k_attn_feat(const float* __restrict__ feature) {
    int b = blockIdx.y;
    __shared__ float sp[PANO_];
    __shared__ float sms[2];
    if (threadIdx.x < PANO_) sp[threadIdx.x] = g_a[b * PANO_ + threadIdx.x];
    __syncthreads();
    if (threadIdx.x == 0) {
        float m = -INFINITY;
        for (int i = 0; i < PANO_; i++) m = fmaxf(m, sp[i]);
        float su = 0.f;
        for (int i = 0; i < PANO_; i++) su += expf(sp[i] - m);
        sms[0] = m; sms[1] = su;
    }
    __syncthreads();
    if (threadIdx.x < PANO_)
        sp[threadIdx.x] = expf(sp[threadIdx.x] - sms[0]) / sms[1];
    __syncthreads();
    int i = blockIdx.x * 256 + threadIdx.x;   // float4 index over 3076/4 = 769
    if (i >= 769) return;
    int d = i * 4;
    float ax = 0.f, ay = 0.f, az = 0.f, aw = 0.f;
    if (d < FEAT_) {
        const float4* f = (const float4*)(feature + (size_t)b * PANO_ * FEAT_) + i;
        #pragma unroll 4
        for (int s = 0; s < PANO_; s++) {
            float4 v = f[(size_t)s * (FEAT_/4)];
            float p = sp[s];
            ax += p*v.x; ay += p*v.y; az += p*v.z; aw += p*v.w;
        }
    } else {
        const float4* f = (const float4*)(g_pano_sim + (size_t)b * PANO_ * 900 + (d - FEAT_));
        #pragma unroll 4
        for (int s = 0; s < PANO_; s++) {
            float4 v = f[(size_t)s * 225];
            float p = sp[s];
            ax += p*v.x; ay += p*v.y; az += p*v.z; aw += p*v.w;
        }
    }
    float4 o; o.x = ax; o.y = ay; o.z = az; o.w = aw;
    *(float4*)(g_x + (size_t)b * 3140 + 64 + d) = o;
}

// ---------------- LSTM (sums ih(5) + hh(4) partials + bias) ----------------
__global__ void k_lstm(const float* __restrict__ c0,
                       const float* __restrict__ bias,
                       float* __restrict__ out) {
    int idx = blockIdx.x * 256 + threadIdx.x;
    if (idx >= B_ * H_) return;
    int b = idx >> 9, j = idx & 511;
    float g4[4];
    #pragma unroll
    for (int qg = 0; qg < 4; qg++) {
        int col = qg * 512 + j;
        float v = bias[col];
        #pragma unroll
        for (int s = 0; s < 5; s++)
            v += g_part[(size_t)s * 64 * 2048 + (size_t)b * 2048 + col];
        #pragma unroll
        for (int s = 0; s < 4; s++)
            v += g_parthh[(size_t)s * 64 * 2048 + (size_t)b * 2048 + col];
        g4[qg] = v;
    }
    float ig = sigmoidf_(g4[0]);
    float fg = sigmoidf_(g4[1]);
    float gg = tanhf(g4[2]);
    float og = sigmoidf_(g4[3]);
    float c1 = fg * c0[idx] + ig * gg;
    float h1 = og * tanhf(c1);
    out[OFF_H1 + idx] = h1;
    out[OFF_C1 + idx] = c1;
}

// ---------------- ctx attention (sums att_in 8 partials inline) ----------------
__global__ void k_ctx_attn(const float* __restrict__ ctx,
                           const unsigned char* __restrict__ cmask,
                           float* __restrict__ out) {
    int b = blockIdx.x;
    int tid = threadIdx.x; // 512
    __shared__ float sqa[H_], slg[CFG_], sattn[CFG_];
    {
        float v = 0.f;
        #pragma unroll
        for (int s = 0; s < 8; s++)
            v += g_part2[(size_t)s * 64 * 512 + (size_t)b * 512 + tid];
        sqa[tid] = v;
    }
    __syncthreads();
    int w = tid >> 5, lane = tid & 31;
    const float* cb = ctx + (size_t)b * CFG_ * H_;
    {
        float acc = 0.f;
        const float* cw = cb + w * H_;
        for (int d = lane; d < H_; d += 32) acc += cw[d] * sqa[d];
        acc = wred(acc);
        if (lane == 0) slg[w] = cmask[b * CFG_ + w] ? -INFINITY : acc;
    }
    __syncthreads();
    if (tid == 0) {
        float m = -INFINITY;
        for (int s = 0; s < CFG_; s++) m = fmaxf(m, slg[s]);
        float su = 0.f;
        for (int s = 0; s < CFG_; s++) { float e = expf(slg[s] - m); sattn[s] = e; su += e; }
        float inv = 1.f / su;
        for (int s = 0; s < CFG_; s++) { sattn[s] *= inv; out[OFF_CA + b * CFG_ + s] = sattn[s]; }
    }
    __syncthreads();
    float acc = 0.f;
    #pragma unroll
    for (int s = 0; s < CFG_; s++) acc += sattn[s] * cb[(size_t)s * H_ + tid];
    g_cat[b * 1024 + tid] = acc;
    g_cat[b * 1024 + 512 + tid] = out[OFF_H1 + b * H_ + tid];
}

// ---------------- h_tilde = tanh(sum of 8 att_out partials) ----------------
__global__ void k_tanh_ht(float* __restrict__ out) {
    int idx = blockIdx.x * 256 + threadIdx.x;
    if (idx >= B_ * H_) return;
    float v = 0.f;
    #pragma unroll
    for (int s = 0; s < 8; s++) v += g_part2[(size_t)s * 64 * 512 + idx];
    out[OFF_HT + idx] = tanhf(v);
}

// ---------------- host launcher ----------------
extern "C" void kernel_launch(void* const* d_in, const int* in_sizes, int n_in,
                              void* d_out, int out_size) {
    const float* action    = (const float*)d_in[0];
    const float* feature   = (const float*)d_in[1];
    const float* cand_feat = (const float*)d_in[2];
    const float* prev_h1   = (const float*)d_in[3];
    const float* c_0       = (const float*)d_in[4];
    const float* ctx       = (const float*)d_in[5];
    const float* s_0       = (const float*)d_in[6];
    const float* land      = (const float*)d_in[7];
    const float* cand_obj  = (const float*)d_in[8];
    const float* lmask     = (const float*)d_in[9];
    const float* landrel   = (const float*)d_in[10];
    const float* relmask   = (const float*)d_in[11];
    const float* crel      = (const float*)d_in[12];
    const float* pano_obj  = (const float*)d_in[13];
    const float* embW      = (const float*)d_in[14];
    const float* embB      = (const float*)d_in[15];
    const float* W_ih      = (const float*)d_in[16];
    const float* W_hh      = (const float*)d_in[17];
    const float* b_lstm    = (const float*)d_in[18];
    const float* feat_in_W = (const float*)d_in[19];
    const float* att_in_W  = (const float*)d_in[20];
    const float* att_out_W = (const float*)d_in[21];
    const float* cand_in_W = (const float*)d_in[22];
    const unsigned char* cmask = (const unsigned char*)d_in[23];
    float* out = (float*)d_out;

    float *p_x, *p_qfeat, *p_q2, *p_part, *p_parthh, *p_part2, *p_a, *p_cat;
    cudaGetSymbolAddress((void**)&p_x,      g_x);
    cudaGetSymbolAddress((void**)&p_qfeat,  g_qfeat);
    cudaGetSymbolAddress((void**)&p_q2,     g_q2);
    cudaGetSymbolAddress((void**)&p_part,   g_part);
    cudaGetSymbolAddress((void**)&p_parthh, g_parthh);
    cudaGetSymbolAddress((void**)&p_part2,  g_part2);
    cudaGetSymbolAddress((void**)&p_a,      g_a);
    cudaGetSymbolAddress((void**)&p_cat,    g_cat);

    // 1) action embedding + topk1
    k_misc1<<<80, 256>>>(action, embW, embB, s_0, lmask, land);

    // 2) qfeat = prev_h1 @ feat_in_W (49jb x 4ky -> g_part)
    //    gates_hh = prev_h1 @ W_hh   (32jb x 4ky -> g_parthh)
    k_gemm_pair64<<<324, 128>>>(prev_h1, 512, feat_in_W, 3076, 512, 128, p_part, 49, 196,
                                prev_h1, 512, W_hh,      2048, 512, 128, p_parthh, 32);

    // 3) reduce qfeat partials (4 sets)
    k_reduce<<<769, 256>>>(p_part, 4, 3076, p_qfeat);

    // 4) pano object retrieval + feature-attention logits (fused)
    k_objret<<<B_ * PANO_, 256>>>(pano_obj, PANO_, land, feature, p_qfeat, nullptr, p_a, 0);

    // 5) attention-weighted feature (softmax inline)
    k_attn_feat<<<dim3(4, B_), 256>>>(feature);

    // 6) gates_ih = x @ W_ih  (32jb x 5ky -> g_part)
    k_gemm64<<<dim3(32, 5), 128>>>(p_x, 3140, W_ih, 2048, 3140, 640, p_part);

    // 7) LSTM pointwise (sums ih(5) + hh(4) partials + bias)
    k_lstm<<<128, 256>>>(c_0, b_lstm, out);

    // 8) qa = h1 @ att_in_W (8jb x 8ky -> g_part2, reduced in ctx_attn)
    k_gemm64<<<dim3(8, 8), 128>>>(out + OFF_H1, 512, att_in_W, 512, 512, 64, p_part2);

    // 9) ctx attention
    k_ctx_attn<<<B_, 512>>>(ctx, cmask, out);

    // 10) att_out GEMM (64 splitK blocks -> g_part2) + topk2 (64 blocks), merged
    k_attout_topk<<<128, 128>>>(p_cat, att_out_W, out + OFF_CA, lmask, land, relmask, landrel);

    // 11) h_tilde = tanh(sum of att_out partials)
    k_tanh_ht<<<128, 256>>>(out);

    // 12) q2 = h_tilde @ cand_in_W (49jb x 4ky -> g_part)
    k_gemm64<<<dim3(49, 4), 128>>>(out + OFF_HT, 512, cand_in_W, 3097, 512, 128, p_part);

    // 13) reduce q2 partials
    k_reduce<<<775, 256>>>(p_part, 4, 3097, p_q2);

    // 14) candidate retrieval + final logit
    k_objret<<<B_ * IMG_, 256>>>(cand_obj, IMG_, land, cand_feat, p_q2, crel, out + OFF_LOG, 1);
}